// round 13
// baseline (speedup 1.0000x reference)
#include <cuda_runtime.h>
#include <cuda_fp16.h>
#include <math.h>
#include <stdint.h>

#define B_ 4096
#define F_ 16
#define H_ 1280
#define N_ 8
#define R_ 64
#define C_ (F_*H_)   // 20480
#define GB 8
#define KSPLIT 16

// ---------------- device scratch ----------------
__device__ float g_gwinv[N_];
__device__ float g_dotp[KSPLIT*B_*8];
__device__ float g_xsqp[KSPLIT*B_];
__device__ int   g_expert[B_];
__device__ int   g_cnt[N_];
__device__ int   g_off[N_+1];
__device__ int   g_perm[B_];

// ---------------- helpers ----------------
__device__ __forceinline__ uint32_t smem_u32(const void* p) {
    uint32_t a;
    asm("{ .reg .u64 t; cvta.to.shared.u64 t, %1; cvt.u32.u64 %0, t; }" : "=r"(a) : "l"(p));
    return a;
}
__device__ __forceinline__ void ldsm_x4(uint32_t* r, uint32_t addr) {
    asm volatile("ldmatrix.sync.aligned.m8n8.x4.shared.b16 {%0,%1,%2,%3}, [%4];"
                 : "=r"(r[0]), "=r"(r[1]), "=r"(r[2]), "=r"(r[3]) : "r"(addr));
}
__device__ __forceinline__ void mma_f16(float* c, const uint32_t* a, const uint32_t* b) {
    asm volatile("mma.sync.aligned.m16n8k16.row.col.f32.f16.f16.f32 "
        "{%0,%1,%2,%3}, {%4,%5,%6,%7}, {%8,%9}, {%0,%1,%2,%3};"
        : "+f"(c[0]), "+f"(c[1]), "+f"(c[2]), "+f"(c[3])
        : "r"(a[0]), "r"(a[1]), "r"(a[2]), "r"(a[3]), "r"(b[0]), "r"(b[1]));
}
__device__ __forceinline__ uint32_t pkh(float lo, float hi) {
    uint32_t r;
    asm("cvt.rn.f16x2.f32 %0, %1, %2;" : "=r"(r) : "f"(hi), "f"(lo));
    return r;
}
__device__ __forceinline__ void split2h(float a, float b, uint32_t& h, uint32_t& l) {
    h = pkh(a, b);
    __half2 hh = *reinterpret_cast<__half2*>(&h);
    float2 f = __half22float2(hh);
    l = pkh(a - f.x, b - f.y);
}
__device__ __forceinline__ void st_hilo(char* hi_p, char* lo_p, float4 v) {
    uint32_t h0, l0, h1, l1;
    split2h(v.x, v.y, h0, l0);
    split2h(v.z, v.w, h1, l1);
    *(uint2*)hi_p = make_uint2(h0, h1);
    *(uint2*)lo_p = make_uint2(l0, l1);
}
__device__ __forceinline__ uint2 cvt_h(float4 v) {
    return make_uint2(pkh(v.x, v.y), pkh(v.z, v.w));
}

#define STRD 144

// ================= k0: gwinv (8 CTAs) + reset counters =================
__global__ __launch_bounds__(256) void k0_prep(const float* __restrict__ gw) {
    __shared__ float red[8];
    int n = blockIdx.x, tid = threadIdx.x;
    if (n == 0 && tid < N_) g_cnt[tid] = 0;
    float s = 0.f;
    const float4* row = (const float4*)(gw + (size_t)n * C_);
    for (int i = tid; i < C_/4; i += 256) {
        float4 v = row[i];
        s += v.x*v.x + v.y*v.y + v.z*v.z + v.w*v.w;
    }
    #pragma unroll
    for (int o = 16; o; o >>= 1) s += __shfl_xor_sync(0xffffffffu, s, o);
    if ((tid & 31) == 0) red[tid >> 5] = s;
    __syncthreads();
    if (tid < 8) {
        s = red[tid];
        #pragma unroll
        for (int o = 4; o; o >>= 1) s += __shfl_xor_sync(0xffu, s, o);
        if (tid == 0) g_gwinv[n] = 1.f / fmaxf(sqrtf(s), 1e-12f);
    }
}

// ================= k1: gating dots via fp16 3-term mma (routing-safe), K-split 16 =================
#define K1_X_HI 0
#define K1_X_LO 18432
#define K1_W_HI 36864
__global__ __launch_bounds__(256, 3) void k1_mma(const float* __restrict__ x,
                                                 const float* __restrict__ gw) {
    __shared__ char sm[36864 + 2*2304];
    const int W_LO_O = 36864 + 2304;

    int tid = threadIdx.x, wid = tid >> 5, lid = tid & 31;
    int b0 = blockIdx.x * 128;
    int kb = blockIdx.y;

    uint32_t sb = smem_u32(sm);
    const float4* x4  = (const float4*)x;
    const float4* gw4 = (const float4*)gw;

    int ldr = tid >> 4;
    int ldc = tid & 15;

    uint32_t aoff = (uint32_t)((16*wid + (lid & 15))*STRD + (lid >> 4)*16);
    uint32_t boff = (uint32_t)(((lid & 7) + ((lid >> 4) & 1)*8)*STRD + ((lid >> 3) & 1)*16);

    float acc[4] = {0.f, 0.f, 0.f, 0.f};
    float sqr[8];
    #pragma unroll
    for (int j = 0; j < 8; j++) sqr[j] = 0.f;

    float4 xg[8], wg;
    #pragma unroll
    for (int j = 0; j < 8; j++) {
        int row = ldr + 16*j;
        xg[j] = __ldcs(&x4[(size_t)(b0 + row)*5120 + kb*320 + ldc]);
    }
    if (tid < 128) wg = gw4[(size_t)(tid >> 4)*5120 + kb*320 + (tid & 15)];
    #pragma unroll
    for (int j = 0; j < 8; j++) {
        int row = ldr + 16*j;
        sqr[j] += xg[j].x*xg[j].x + xg[j].y*xg[j].y + xg[j].z*xg[j].z + xg[j].w*xg[j].w;
        st_hilo(sm + K1_X_HI + row*STRD + ldc*8, sm + K1_X_LO + row*STRD + ldc*8, xg[j]);
    }
    if (tid < 128)
        st_hilo(sm + K1_W_HI + (tid >> 4)*STRD + (tid & 15)*8,
                sm + W_LO_O + (tid >> 4)*STRD + (tid & 15)*8, wg);
    __syncthreads();

    for (int ch = 0; ch < 20; ch++) {
        if (ch + 1 < 20) {
            #pragma unroll
            for (int j = 0; j < 8; j++) {
                int row = ldr + 16*j;
                xg[j] = __ldcs(&x4[(size_t)(b0 + row)*5120 + kb*320 + (ch+1)*16 + ldc]);
            }
            if (tid < 128) wg = gw4[(size_t)(tid >> 4)*5120 + kb*320 + (ch+1)*16 + (tid & 15)];
        }
        #pragma unroll
        for (int ks = 0; ks < 4; ks++) {
            uint32_t ah[4], al[4], bh[4], bl[4];
            ldsm_x4(ah, sb + K1_X_HI + aoff + ks*32);
            ldsm_x4(al, sb + K1_X_LO + aoff + ks*32);
            ldsm_x4(bh, sb + K1_W_HI + boff + ks*32);
            ldsm_x4(bl, sb + W_LO_O + boff + ks*32);
            mma_f16(acc, ah, bh);
            mma_f16(acc, al, bh);
            mma_f16(acc, ah, bl);
        }
        __syncthreads();
        if (ch + 1 < 20) {
            #pragma unroll
            for (int j = 0; j < 8; j++) {
                int row = ldr + 16*j;
                sqr[j] += xg[j].x*xg[j].x + xg[j].y*xg[j].y + xg[j].z*xg[j].z + xg[j].w*xg[j].w;
                st_hilo(sm + K1_X_HI + row*STRD + ldc*8, sm + K1_X_LO + row*STRD + ldc*8, xg[j]);
            }
            if (tid < 128)
                st_hilo(sm + K1_W_HI + (tid >> 4)*STRD + (tid & 15)*8,
                        sm + W_LO_O + (tid >> 4)*STRD + (tid & 15)*8, wg);
            __syncthreads();
        }
    }

    #pragma unroll
    for (int j = 0; j < 8; j++) {
        float s = sqr[j];
        #pragma unroll
        for (int o = 8; o; o >>= 1) s += __shfl_xor_sync(0xffffffffu, s, o);
        sqr[j] = s;
    }
    if ((tid & 15) == 0) {
        #pragma unroll
        for (int j = 0; j < 8; j++)
            g_xsqp[(size_t)kb*B_ + b0 + ldr + 16*j] = sqr[j];
    }
    {
        int r = lid >> 2, n0 = 2*(lid & 3);
        int m0 = b0 + wid*16 + r;
        float2* dp = (float2*)g_dotp;
        dp[(((size_t)kb*B_ + m0)*8 + n0) >> 1]     = make_float2(acc[0], acc[1]);
        dp[(((size_t)kb*B_ + m0 + 8)*8 + n0) >> 1] = make_float2(acc[2], acc[3]);
    }
}

// ================= k1b: sum partials + logits + gumbel + argmax (16 CTAs) =================
__global__ void k1b_argmax(const float* __restrict__ u, const float* __restrict__ sigma_p) {
    int b = blockIdx.x * blockDim.x + threadIdx.x;
    if (b >= B_) return;
    float sigma = *sigma_p;
    float d[8];
    #pragma unroll
    for (int n = 0; n < 8; n++) d[n] = 0.f;
    float xs = 0.f;
    #pragma unroll
    for (int kb = 0; kb < KSPLIT; kb++) {
        const float4* p = (const float4*)(g_dotp + ((size_t)kb*B_ + b)*8);
        float4 a = p[0], c = p[1];
        d[0] += a.x; d[1] += a.y; d[2] += a.z; d[3] += a.w;
        d[4] += c.x; d[5] += c.y; d[6] += c.z; d[7] += c.w;
        xs += g_xsqp[(size_t)kb*B_ + b];
    }
    float invx = 1.f / fmaxf(sqrtf(xs), 1e-12f);
    const float4* u4 = (const float4*)(u + (size_t)b*8);
    float4 ua = u4[0], ub = u4[1];
    float uu[8] = {ua.x, ua.y, ua.z, ua.w, ub.x, ub.y, ub.z, ub.w};
    float best = -3.4e38f; int e = 0;
    #pragma unroll
    for (int n = 0; n < 8; n++) {
        float logit = sigma * d[n] * invx * g_gwinv[n];
        float gmb = -logf(-logf(uu[n] + 1e-12f) + 1e-12f);
        float z = logit + gmb;
        if (z > best) { best = z; e = n; }
    }
    g_expert[b] = e;
    atomicAdd(&g_cnt[e], 1);
}

// ================= k1cd: scan + scatter (one CTA, int work only) =================
__global__ __launch_bounds__(512) void k1cd() {
    __shared__ int cur_s[N_];
    int tid = threadIdx.x;
    if (tid == 0) {
        int a = 0;
        #pragma unroll
        for (int n = 0; n < N_; n++) { g_off[n] = a; cur_s[n] = a; a += g_cnt[n]; }
        g_off[N_] = a;
    }
    __syncthreads();
    for (int b = tid; b < B_; b += 512) {
        int e = g_expert[b];
        int pos = atomicAdd(&cur_s[e], 1);
        g_perm[pos] = b;
    }
}

// ================= K3: fused warp-mma LoRA, fp16-at-load prefetch, 3 CTAs/SM =================
// smem: X_HI/MID_HI 0..18432, W_B0 18432..27648, W_B1 27648..36864
#define X_HI   0
#define MID_HI 0
#define W_B0   18432
#define W_B1   27648
#define DYN_SMEM 36864

__global__ __launch_bounds__(256, 3)
void k3_mma(const float* __restrict__ x, const float* __restrict__ dw,
            const float* __restrict__ uw, float* __restrict__ out) {
    extern __shared__ char sm[];
    __shared__ int bs_sh[GB];
    __shared__ int info[2];

    int tid = threadIdx.x, wid = tid >> 5, lid = tid & 31;

    if (tid == 0) {
        int rem = blockIdx.x; int e = -1, g = 0, start = 0;
        for (int n = 0; n < N_; n++) {
            int cnt = g_off[n+1] - g_off[n];
            int ng = (cnt + GB - 1) / GB;
            if (rem < ng) { e = n; start = g_off[n] + rem*GB;
                            g = g_off[n+1] - start; if (g > GB) g = GB; break; }
            rem -= ng;
        }
        info[0] = e; info[1] = g;
        if (e >= 0) for (int i = 0; i < GB; i++) {
            int ii = i < g ? i : g - 1;
            bs_sh[i] = g_perm[start + ii];
        }
    }
    __syncthreads();
    int e = info[0], g = info[1];
    if (e < 0) return;

    uint32_t sb = smem_u32(sm);
    const float4* x4  = (const float4*)x;
    const float4* dw4 = (const float4*)dw;
    const float4* uw4 = (const float4*)uw;

    int ldr = tid >> 4;
    int ldc = tid & 15;

    uint32_t aoff = (uint32_t)((16*wid + (lid & 15))*STRD + (lid >> 4)*16);
    uint32_t boff = (uint32_t)(((lid & 7) + ((lid >> 4) & 1)*8)*STRD + ((lid >> 3) & 1)*16);

    // ---------------- phase 1: fp16-converted-at-load prefetch ----------------
    float acc[8][4];
    #pragma unroll
    for (int i = 0; i < 8; i++)
        #pragma unroll
        for (int j = 0; j < 4; j++) acc[i][j] = 0.f;

    uint2 xh[8], wh[4];
    #pragma unroll
    for (int j = 0; j < 8; j++) {
        int row = ldr + 16*j;
        int bb = bs_sh[row >> 4], f = row & 15;
        xh[j] = cvt_h(__ldcs(&x4[(size_t)(bb*16 + f)*320 + ldc]));
    }
    #pragma unroll
    for (int j = 0; j < 4; j++) {
        int row = ldr + 16*j;
        wh[j] = cvt_h(dw4[(size_t)(e*64 + row)*320 + ldc]);
    }
    #pragma unroll
    for (int j = 0; j < 8; j++) {
        int row = ldr + 16*j;
        *(uint2*)(sm + X_HI + row*STRD + ldc*8) = xh[j];
    }
    #pragma unroll
    for (int j = 0; j < 4; j++) {
        int row = ldr + 16*j;
        *(uint2*)(sm + W_B0 + row*STRD + ldc*8) = wh[j];
    }
    __syncthreads();

    for (int ch = 0; ch < 20; ch++) {
        if (ch + 1 < 20) {
            #pragma unroll
            for (int j = 0; j < 8; j++) {
                int row = ldr + 16*j;
                int bb = bs_sh[row >> 4], f = row & 15;
                xh[j] = cvt_h(__ldcs(&x4[(size_t)(bb*16 + f)*320 + (ch+1)*16 + ldc]));
            }
            #pragma unroll
            for (int j = 0; j < 4; j++) {
                int row = ldr + 16*j;
                wh[j] = cvt_h(dw4[(size_t)(e*64 + row)*320 + (ch+1)*16 + ldc]);
            }
        }
        #pragma unroll
        for (int ks = 0; ks < 4; ks++) {
            uint32_t ah[4];
            ldsm_x4(ah, sb + X_HI + aoff + ks*32);
            #pragma unroll
            for (int np = 0; np < 4; np++) {
                uint32_t bh[4];
                ldsm_x4(bh, sb + W_B0 + boff + np*16*STRD + ks*32);
                mma_f16(acc[2*np],   ah, bh);
                mma_f16(acc[2*np+1], ah, bh+2);
            }
        }
        __syncthreads();
        if (ch + 1 < 20) {
            #pragma unroll
            for (int j = 0; j < 8; j++) {
                int row = ldr + 16*j;
                *(uint2*)(sm + X_HI + row*STRD + ldc*8) = xh[j];
            }
            #pragma unroll
            for (int j = 0; j < 4; j++) {
                int row = ldr + 16*j;
                *(uint2*)(sm + W_B0 + row*STRD + ldc*8) = wh[j];
            }
            __syncthreads();
        }
    }

    // ---------------- mid -> smem fp16 ----------------
    {
        int r0 = 16*wid + (lid >> 2);
        int co = (lid & 3)*4;
        #pragma unroll
        for (int nt = 0; nt < 8; nt++) {
            *(uint32_t*)(sm + MID_HI + r0*STRD + nt*16 + co)     = pkh(acc[nt][0], acc[nt][1]);
            *(uint32_t*)(sm + MID_HI + (r0+8)*STRD + nt*16 + co) = pkh(acc[nt][2], acc[nt][3]);
        }
    }
    __syncthreads();

    uint32_t mah[4][4];
    #pragma unroll
    for (int ks = 0; ks < 4; ks++)
        ldsm_x4(mah[ks], sb + MID_HI + aoff + ks*32);

    // ---------------- phase 2: double-buffered W ----------------
    int bb_w = bs_sh[wid];
    float* outw = out + (size_t)(bb_w*16)*1280;

    #pragma unroll
    for (int j = 0; j < 4; j++) {
        int row = ldr + 16*j;
        wh[j] = cvt_h(uw4[(size_t)(e*1280 + row)*16 + ldc]);
    }
    #pragma unroll
    for (int j = 0; j < 4; j++) {
        int row = ldr + 16*j;
        *(uint2*)(sm + W_B0 + row*STRD + ldc*8) = wh[j];
    }
    __syncthreads();

    for (int i = 0; i < 20; i++) {
        uint32_t buf = (i & 1) ? W_B1 : W_B0;
        if (i + 1 < 20) {
            #pragma unroll
            for (int j = 0; j < 4; j++) {
                int row = ldr + 16*j;
                wh[j] = cvt_h(uw4[(size_t)(e*1280 + (i+1)*64 + row)*16 + ldc]);
            }
        }
        float a2[8][4];
        #pragma unroll
        for (int p = 0; p < 8; p++)
            #pragma unroll
            for (int q = 0; q < 4; q++) a2[p][q] = 0.f;
        #pragma unroll
        for (int ks = 0; ks < 4; ks++) {
            #pragma unroll
            for (int np = 0; np < 4; np++) {
                uint32_t bh[4];
                ldsm_x4(bh, sb + buf + boff + np*16*STRD + ks*32);
                mma_f16(a2[2*np],   mah[ks], bh);
                mma_f16(a2[2*np+1], mah[ks], bh+2);
            }
        }
        if (wid < g) {
            int r0 = lid >> 2, c0 = (lid & 3)*2;
            #pragma unroll
            for (int nt = 0; nt < 8; nt++) {
                int col = i*64 + nt*8 + c0;
                __stcs((float2*)(outw + (size_t)r0*1280 + col),     make_float2(a2[nt][0], a2[nt][1]));
                __stcs((float2*)(outw + (size_t)(r0+8)*1280 + col), make_float2(a2[nt][2], a2[nt][3]));
            }
        }
        if (i + 1 < 20) {
            uint32_t nbuf = ((i+1) & 1) ? W_B1 : W_B0;
            #pragma unroll
            for (int j = 0; j < 4; j++) {
                int row = ldr + 16*j;
                *(uint2*)(sm + nbuf + row*STRD + ldc*8) = wh[j];
            }
            __syncthreads();
        }
    }
}

// ================= launch =================
extern "C" void kernel_launch(void* const* d_in, const int* in_sizes, int n_in,
                              void* d_out, int out_size) {
    const float* x     = (const float*)d_in[0];
    const float* u     = (const float*)d_in[1];
    const float* gw    = (const float*)d_in[2];
    const float* sigma = (const float*)d_in[3];
    const float* dw    = (const float*)d_in[4];
    const float* uw    = (const float*)d_in[5];
    float* out = (float*)d_out;

    cudaFuncSetAttribute(k3_mma, cudaFuncAttributeMaxDynamicSharedMemorySize, DYN_SMEM);

    k0_prep<<<N_, 256>>>(gw);
    k1_mma<<<dim3(32, 16), 256>>>(x, gw);
    k1b_argmax<<<B_/256, 256>>>(u, sigma);
    k1cd<<<1, 512>>>();
    k3_mma<<<B_/GB + N_, 256, DYN_SMEM>>>(x, dw, uw, out);
}

// round 14
// speedup vs baseline: 1.1525x; 1.1525x over previous
#include <cuda_runtime.h>
#include <cuda_fp16.h>
#include <math.h>
#include <stdint.h>

#define B_ 4096
#define F_ 16
#define H_ 1280
#define N_ 8
#define R_ 64
#define C_ (F_*H_)   // 20480
#define GB 8
#define KSPLIT 16

// ---------------- device scratch ----------------
__device__ float g_gwinv[N_];
__device__ float g_dotp[KSPLIT*B_*8];
__device__ float g_xsqp[KSPLIT*B_];
__device__ int   g_expert[B_];
__device__ int   g_cnt[N_];
__device__ int   g_off[N_+1];
__device__ int   g_perm[B_];

// ---------------- helpers ----------------
__device__ __forceinline__ uint32_t smem_u32(const void* p) {
    uint32_t a;
    asm("{ .reg .u64 t; cvta.to.shared.u64 t, %1; cvt.u32.u64 %0, t; }" : "=r"(a) : "l"(p));
    return a;
}
__device__ __forceinline__ void ldsm_x4(uint32_t* r, uint32_t addr) {
    asm volatile("ldmatrix.sync.aligned.m8n8.x4.shared.b16 {%0,%1,%2,%3}, [%4];"
                 : "=r"(r[0]), "=r"(r[1]), "=r"(r[2]), "=r"(r[3]) : "r"(addr));
}
__device__ __forceinline__ void mma_f16(float* c, const uint32_t* a, const uint32_t* b) {
    asm volatile("mma.sync.aligned.m16n8k16.row.col.f32.f16.f16.f32 "
        "{%0,%1,%2,%3}, {%4,%5,%6,%7}, {%8,%9}, {%0,%1,%2,%3};"
        : "+f"(c[0]), "+f"(c[1]), "+f"(c[2]), "+f"(c[3])
        : "r"(a[0]), "r"(a[1]), "r"(a[2]), "r"(a[3]), "r"(b[0]), "r"(b[1]));
}
__device__ __forceinline__ uint32_t pkh(float lo, float hi) {
    uint32_t r;
    asm("cvt.rn.f16x2.f32 %0, %1, %2;" : "=r"(r) : "f"(hi), "f"(lo));
    return r;
}
__device__ __forceinline__ void split2h(float a, float b, uint32_t& h, uint32_t& l) {
    h = pkh(a, b);
    __half2 hh = *reinterpret_cast<__half2*>(&h);
    float2 f = __half22float2(hh);
    l = pkh(a - f.x, b - f.y);
}
__device__ __forceinline__ void st_hilo(char* hi_p, char* lo_p, float4 v) {
    uint32_t h0, l0, h1, l1;
    split2h(v.x, v.y, h0, l0);
    split2h(v.z, v.w, h1, l1);
    *(uint2*)hi_p = make_uint2(h0, h1);
    *(uint2*)lo_p = make_uint2(l0, l1);
}
__device__ __forceinline__ void st_hi(char* hi_p, float4 v) {
    uint32_t h0 = pkh(v.x, v.y);
    uint32_t h1 = pkh(v.z, v.w);
    *(uint2*)hi_p = make_uint2(h0, h1);
}

#define STRD 144

// ================= k0: gwinv (8 CTAs) + reset counters =================
__global__ __launch_bounds__(256) void k0_prep(const float* __restrict__ gw) {
    __shared__ float red[8];
    int n = blockIdx.x, tid = threadIdx.x;
    if (n == 0 && tid < N_) g_cnt[tid] = 0;
    float s = 0.f;
    const float4* row = (const float4*)(gw + (size_t)n * C_);
    for (int i = tid; i < C_/4; i += 256) {
        float4 v = row[i];
        s += v.x*v.x + v.y*v.y + v.z*v.z + v.w*v.w;
    }
    #pragma unroll
    for (int o = 16; o; o >>= 1) s += __shfl_xor_sync(0xffffffffu, s, o);
    if ((tid & 31) == 0) red[tid >> 5] = s;
    __syncthreads();
    if (tid < 8) {
        s = red[tid];
        #pragma unroll
        for (int o = 4; o; o >>= 1) s += __shfl_xor_sync(0xffu, s, o);
        if (tid == 0) g_gwinv[n] = 1.f / fmaxf(sqrtf(s), 1e-12f);
    }
}

// ================= k1: gating dots via fp16 3-term mma (routing-safe), K-split 16 =================
#define K1_X_HI 0
#define K1_X_LO 18432
#define K1_W_HI 36864
__global__ __launch_bounds__(256, 3) void k1_mma(const float* __restrict__ x,
                                                 const float* __restrict__ gw) {
    __shared__ char sm[36864 + 2*2304];
    const int W_LO_O = 36864 + 2304;

    int tid = threadIdx.x, wid = tid >> 5, lid = tid & 31;
    int b0 = blockIdx.x * 128;
    int kb = blockIdx.y;

    uint32_t sb = smem_u32(sm);
    const float4* x4  = (const float4*)x;
    const float4* gw4 = (const float4*)gw;

    int ldr = tid >> 4;
    int ldc = tid & 15;

    uint32_t aoff = (uint32_t)((16*wid + (lid & 15))*STRD + (lid >> 4)*16);
    uint32_t boff = (uint32_t)(((lid & 7) + ((lid >> 4) & 1)*8)*STRD + ((lid >> 3) & 1)*16);

    float acc[4] = {0.f, 0.f, 0.f, 0.f};
    float sqr[8];
    #pragma unroll
    for (int j = 0; j < 8; j++) sqr[j] = 0.f;

    float4 xg[8], wg;
    #pragma unroll
    for (int j = 0; j < 8; j++) {
        int row = ldr + 16*j;
        xg[j] = __ldcs(&x4[(size_t)(b0 + row)*5120 + kb*320 + ldc]);
    }
    if (tid < 128) wg = gw4[(size_t)(tid >> 4)*5120 + kb*320 + (tid & 15)];
    #pragma unroll
    for (int j = 0; j < 8; j++) {
        int row = ldr + 16*j;
        sqr[j] += xg[j].x*xg[j].x + xg[j].y*xg[j].y + xg[j].z*xg[j].z + xg[j].w*xg[j].w;
        st_hilo(sm + K1_X_HI + row*STRD + ldc*8, sm + K1_X_LO + row*STRD + ldc*8, xg[j]);
    }
    if (tid < 128)
        st_hilo(sm + K1_W_HI + (tid >> 4)*STRD + (tid & 15)*8,
                sm + W_LO_O + (tid >> 4)*STRD + (tid & 15)*8, wg);
    __syncthreads();

    for (int ch = 0; ch < 20; ch++) {
        if (ch + 1 < 20) {
            #pragma unroll
            for (int j = 0; j < 8; j++) {
                int row = ldr + 16*j;
                xg[j] = __ldcs(&x4[(size_t)(b0 + row)*5120 + kb*320 + (ch+1)*16 + ldc]);
            }
            if (tid < 128) wg = gw4[(size_t)(tid >> 4)*5120 + kb*320 + (ch+1)*16 + (tid & 15)];
        }
        #pragma unroll
        for (int ks = 0; ks < 4; ks++) {
            uint32_t ah[4], al[4], bh[4], bl[4];
            ldsm_x4(ah, sb + K1_X_HI + aoff + ks*32);
            ldsm_x4(al, sb + K1_X_LO + aoff + ks*32);
            ldsm_x4(bh, sb + K1_W_HI + boff + ks*32);
            ldsm_x4(bl, sb + W_LO_O + boff + ks*32);
            mma_f16(acc, ah, bh);
            mma_f16(acc, al, bh);
            mma_f16(acc, ah, bl);
        }
        __syncthreads();
        if (ch + 1 < 20) {
            #pragma unroll
            for (int j = 0; j < 8; j++) {
                int row = ldr + 16*j;
                sqr[j] += xg[j].x*xg[j].x + xg[j].y*xg[j].y + xg[j].z*xg[j].z + xg[j].w*xg[j].w;
                st_hilo(sm + K1_X_HI + row*STRD + ldc*8, sm + K1_X_LO + row*STRD + ldc*8, xg[j]);
            }
            if (tid < 128)
                st_hilo(sm + K1_W_HI + (tid >> 4)*STRD + (tid & 15)*8,
                        sm + W_LO_O + (tid >> 4)*STRD + (tid & 15)*8, wg);
            __syncthreads();
        }
    }

    #pragma unroll
    for (int j = 0; j < 8; j++) {
        float s = sqr[j];
        #pragma unroll
        for (int o = 8; o; o >>= 1) s += __shfl_xor_sync(0xffffffffu, s, o);
        sqr[j] = s;
    }
    if ((tid & 15) == 0) {
        #pragma unroll
        for (int j = 0; j < 8; j++)
            g_xsqp[(size_t)kb*B_ + b0 + ldr + 16*j] = sqr[j];
    }
    {
        int r = lid >> 2, n0 = 2*(lid & 3);
        int m0 = b0 + wid*16 + r;
        float2* dp = (float2*)g_dotp;
        dp[(((size_t)kb*B_ + m0)*8 + n0) >> 1]     = make_float2(acc[0], acc[1]);
        dp[(((size_t)kb*B_ + m0 + 8)*8 + n0) >> 1] = make_float2(acc[2], acc[3]);
    }
}

// ================= k1b: sum partials + logits + gumbel + argmax (16 CTAs) =================
__global__ void k1b_argmax(const float* __restrict__ u, const float* __restrict__ sigma_p) {
    int b = blockIdx.x * blockDim.x + threadIdx.x;
    if (b >= B_) return;
    float sigma = *sigma_p;
    float d[8];
    #pragma unroll
    for (int n = 0; n < 8; n++) d[n] = 0.f;
    float xs = 0.f;
    #pragma unroll
    for (int kb = 0; kb < KSPLIT; kb++) {
        const float4* p = (const float4*)(g_dotp + ((size_t)kb*B_ + b)*8);
        float4 a = p[0], c = p[1];
        d[0] += a.x; d[1] += a.y; d[2] += a.z; d[3] += a.w;
        d[4] += c.x; d[5] += c.y; d[6] += c.z; d[7] += c.w;
        xs += g_xsqp[(size_t)kb*B_ + b];
    }
    float invx = 1.f / fmaxf(sqrtf(xs), 1e-12f);
    const float4* u4 = (const float4*)(u + (size_t)b*8);
    float4 ua = u4[0], ub = u4[1];
    float uu[8] = {ua.x, ua.y, ua.z, ua.w, ub.x, ub.y, ub.z, ub.w};
    float best = -3.4e38f; int e = 0;
    #pragma unroll
    for (int n = 0; n < 8; n++) {
        float logit = sigma * d[n] * invx * g_gwinv[n];
        float gmb = -logf(-logf(uu[n] + 1e-12f) + 1e-12f);
        float z = logit + gmb;
        if (z > best) { best = z; e = n; }
    }
    g_expert[b] = e;
    atomicAdd(&g_cnt[e], 1);
}

// ================= k1cd: scan + scatter (one CTA, int work only) =================
__global__ __launch_bounds__(512) void k1cd() {
    __shared__ int cur_s[N_];
    int tid = threadIdx.x;
    if (tid == 0) {
        int a = 0;
        #pragma unroll
        for (int n = 0; n < N_; n++) { g_off[n] = a; cur_s[n] = a; a += g_cnt[n]; }
        g_off[N_] = a;
    }
    __syncthreads();
    for (int b = tid; b < B_; b += 512) {
        int e = g_expert[b];
        int pos = atomicAdd(&cur_s[e], 1);
        g_perm[pos] = b;
    }
}

// ================= K3: fused warp-mma LoRA, single-fp16 operands (round-12 winner) =================
// smem: X_HI/MID_HI 0..18432, W_B0 18432..27648, W_B1 27648..36864
#define X_HI   0
#define MID_HI 0
#define W_B0   18432
#define W_B1   27648
#define DYN_SMEM 36864

__global__ __launch_bounds__(256, 2)
void k3_mma(const float* __restrict__ x, const float* __restrict__ dw,
            const float* __restrict__ uw, float* __restrict__ out) {
    extern __shared__ char sm[];
    __shared__ int bs_sh[GB];
    __shared__ int info[2];

    int tid = threadIdx.x, wid = tid >> 5, lid = tid & 31;

    if (tid == 0) {
        int rem = blockIdx.x; int e = -1, g = 0, start = 0;
        for (int n = 0; n < N_; n++) {
            int cnt = g_off[n+1] - g_off[n];
            int ng = (cnt + GB - 1) / GB;
            if (rem < ng) { e = n; start = g_off[n] + rem*GB;
                            g = g_off[n+1] - start; if (g > GB) g = GB; break; }
            rem -= ng;
        }
        info[0] = e; info[1] = g;
        if (e >= 0) for (int i = 0; i < GB; i++) {
            int ii = i < g ? i : g - 1;
            bs_sh[i] = g_perm[start + ii];
        }
    }
    __syncthreads();
    int e = info[0], g = info[1];
    if (e < 0) return;

    uint32_t sb = smem_u32(sm);
    const float4* x4  = (const float4*)x;
    const float4* dw4 = (const float4*)dw;
    const float4* uw4 = (const float4*)uw;

    int ldr = tid >> 4;
    int ldc = tid & 15;

    uint32_t aoff = (uint32_t)((16*wid + (lid & 15))*STRD + (lid >> 4)*16);
    uint32_t boff = (uint32_t)(((lid & 7) + ((lid >> 4) & 1)*8)*STRD + ((lid >> 3) & 1)*16);

    // ---------------- phase 1: single-fp16 X and W ----------------
    float acc[8][4];
    #pragma unroll
    for (int i = 0; i < 8; i++)
        #pragma unroll
        for (int j = 0; j < 4; j++) acc[i][j] = 0.f;

    float4 xg[8], wg[4];
    #pragma unroll
    for (int j = 0; j < 8; j++) {
        int row = ldr + 16*j;
        int bb = bs_sh[row >> 4], f = row & 15;
        xg[j] = __ldcs(&x4[(size_t)(bb*16 + f)*320 + ldc]);
    }
    #pragma unroll
    for (int j = 0; j < 4; j++) {
        int row = ldr + 16*j;
        wg[j] = dw4[(size_t)(e*64 + row)*320 + ldc];
    }
    #pragma unroll
    for (int j = 0; j < 8; j++) {
        int row = ldr + 16*j;
        st_hi(sm + X_HI + row*STRD + ldc*8, xg[j]);
    }
    #pragma unroll
    for (int j = 0; j < 4; j++) {
        int row = ldr + 16*j;
        st_hi(sm + W_B0 + row*STRD + ldc*8, wg[j]);
    }
    __syncthreads();

    for (int ch = 0; ch < 20; ch++) {
        if (ch + 1 < 20) {
            #pragma unroll
            for (int j = 0; j < 8; j++) {
                int row = ldr + 16*j;
                int bb = bs_sh[row >> 4], f = row & 15;
                xg[j] = __ldcs(&x4[(size_t)(bb*16 + f)*320 + (ch+1)*16 + ldc]);
            }
            #pragma unroll
            for (int j = 0; j < 4; j++) {
                int row = ldr + 16*j;
                wg[j] = dw4[(size_t)(e*64 + row)*320 + (ch+1)*16 + ldc];
            }
        }
        #pragma unroll
        for (int ks = 0; ks < 4; ks++) {
            uint32_t ah[4];
            ldsm_x4(ah, sb + X_HI + aoff + ks*32);
            #pragma unroll
            for (int np = 0; np < 4; np++) {
                uint32_t bh[4];
                ldsm_x4(bh, sb + W_B0 + boff + np*16*STRD + ks*32);
                mma_f16(acc[2*np],   ah, bh);
                mma_f16(acc[2*np+1], ah, bh+2);
            }
        }
        __syncthreads();
        if (ch + 1 < 20) {
            #pragma unroll
            for (int j = 0; j < 8; j++) {
                int row = ldr + 16*j;
                st_hi(sm + X_HI + row*STRD + ldc*8, xg[j]);
            }
            #pragma unroll
            for (int j = 0; j < 4; j++) {
                int row = ldr + 16*j;
                st_hi(sm + W_B0 + row*STRD + ldc*8, wg[j]);
            }
            __syncthreads();
        }
    }

    // ---------------- mid -> smem fp16 (single) ----------------
    {
        int r0 = 16*wid + (lid >> 2);
        int co = (lid & 3)*4;
        #pragma unroll
        for (int nt = 0; nt < 8; nt++) {
            *(uint32_t*)(sm + MID_HI + r0*STRD + nt*16 + co)     = pkh(acc[nt][0], acc[nt][1]);
            *(uint32_t*)(sm + MID_HI + (r0+8)*STRD + nt*16 + co) = pkh(acc[nt][2], acc[nt][3]);
        }
    }
    __syncthreads();

    uint32_t mah[4][4];
    #pragma unroll
    for (int ks = 0; ks < 4; ks++)
        ldsm_x4(mah[ks], sb + MID_HI + aoff + ks*32);

    // ---------------- phase 2: double-buffered W, single-fp16 mid ----------------
    int bb_w = bs_sh[wid];
    float* outw = out + (size_t)(bb_w*16)*1280;

    #pragma unroll
    for (int j = 0; j < 4; j++) {
        int row = ldr + 16*j;
        wg[j] = uw4[(size_t)(e*1280 + row)*16 + ldc];
    }
    #pragma unroll
    for (int j = 0; j < 4; j++) {
        int row = ldr + 16*j;
        st_hi(sm + W_B0 + row*STRD + ldc*8, wg[j]);
    }
    __syncthreads();

    for (int i = 0; i < 20; i++) {
        uint32_t buf = (i & 1) ? W_B1 : W_B0;
        if (i + 1 < 20) {
            #pragma unroll
            for (int j = 0; j < 4; j++) {
                int row = ldr + 16*j;
                wg[j] = uw4[(size_t)(e*1280 + (i+1)*64 + row)*16 + ldc];
            }
        }
        float a2[8][4];
        #pragma unroll
        for (int p = 0; p < 8; p++)
            #pragma unroll
            for (int q = 0; q < 4; q++) a2[p][q] = 0.f;
        #pragma unroll
        for (int ks = 0; ks < 4; ks++) {
            #pragma unroll
            for (int np = 0; np < 4; np++) {
                uint32_t bh[4];
                ldsm_x4(bh, sb + buf + boff + np*16*STRD + ks*32);
                mma_f16(a2[2*np],   mah[ks], bh);
                mma_f16(a2[2*np+1], mah[ks], bh+2);
            }
        }
        if (wid < g) {
            int r0 = lid >> 2, c0 = (lid & 3)*2;
            #pragma unroll
            for (int nt = 0; nt < 8; nt++) {
                int col = i*64 + nt*8 + c0;
                __stcs((float2*)(outw + (size_t)r0*1280 + col),     make_float2(a2[nt][0], a2[nt][1]));
                __stcs((float2*)(outw + (size_t)(r0+8)*1280 + col), make_float2(a2[nt][2], a2[nt][3]));
            }
        }
        if (i + 1 < 20) {
            uint32_t nbuf = ((i+1) & 1) ? W_B1 : W_B0;
            #pragma unroll
            for (int j = 0; j < 4; j++) {
                int row = ldr + 16*j;
                st_hi(sm + nbuf + row*STRD + ldc*8, wg[j]);
            }
            __syncthreads();
        }
    }
}

// ================= launch =================
extern "C" void kernel_launch(void* const* d_in, const int* in_sizes, int n_in,
                              void* d_out, int out_size) {
    const float* x     = (const float*)d_in[0];
    const float* u     = (const float*)d_in[1];
    const float* gw    = (const float*)d_in[2];
    const float* sigma = (const float*)d_in[3];
    const float* dw    = (const float*)d_in[4];
    const float* uw    = (const float*)d_in[5];
    float* out = (float*)d_out;

    cudaFuncSetAttribute(k3_mma, cudaFuncAttributeMaxDynamicSharedMemorySize, DYN_SMEM);

    k0_prep<<<N_, 256>>>(gw);
    k1_mma<<<dim3(32, 16), 256>>>(x, gw);
    k1b_argmax<<<B_/256, 256>>>(u, sigma);
    k1cd<<<1, 512>>>();
    k3_mma<<<B_/GB + N_, 256, DYN_SMEM>>>(x, dw, uw, out);
}

// round 15
// speedup vs baseline: 1.1709x; 1.0159x over previous
#include <cuda_runtime.h>
#include <cuda_fp16.h>
#include <math.h>
#include <stdint.h>

#define B_ 4096
#define F_ 16
#define H_ 1280
#define N_ 8
#define R_ 64
#define C_ (F_*H_)   // 20480
#define GB 8
#define KSPLIT 16

// ---------------- device scratch ----------------
__device__ float g_gwinv[N_];
__device__ float g_dotp[KSPLIT*B_*8];
__device__ float g_xsqp[KSPLIT*B_];
__device__ int   g_cnt[N_];
__device__ int   g_perm[N_*B_];   // per-expert fixed regions; order within region irrelevant

// ---------------- helpers ----------------
__device__ __forceinline__ uint32_t smem_u32(const void* p) {
    uint32_t a;
    asm("{ .reg .u64 t; cvta.to.shared.u64 t, %1; cvt.u32.u64 %0, t; }" : "=r"(a) : "l"(p));
    return a;
}
__device__ __forceinline__ void ldsm_x4(uint32_t* r, uint32_t addr) {
    asm volatile("ldmatrix.sync.aligned.m8n8.x4.shared.b16 {%0,%1,%2,%3}, [%4];"
                 : "=r"(r[0]), "=r"(r[1]), "=r"(r[2]), "=r"(r[3]) : "r"(addr));
}
__device__ __forceinline__ void mma_f16(float* c, const uint32_t* a, const uint32_t* b) {
    asm volatile("mma.sync.aligned.m16n8k16.row.col.f32.f16.f16.f32 "
        "{%0,%1,%2,%3}, {%4,%5,%6,%7}, {%8,%9}, {%0,%1,%2,%3};"
        : "+f"(c[0]), "+f"(c[1]), "+f"(c[2]), "+f"(c[3])
        : "r"(a[0]), "r"(a[1]), "r"(a[2]), "r"(a[3]), "r"(b[0]), "r"(b[1]));
}
__device__ __forceinline__ uint32_t pkh(float lo, float hi) {
    uint32_t r;
    asm("cvt.rn.f16x2.f32 %0, %1, %2;" : "=r"(r) : "f"(hi), "f"(lo));
    return r;
}
__device__ __forceinline__ void split2h(float a, float b, uint32_t& h, uint32_t& l) {
    h = pkh(a, b);
    __half2 hh = *reinterpret_cast<__half2*>(&h);
    float2 f = __half22float2(hh);
    l = pkh(a - f.x, b - f.y);
}
__device__ __forceinline__ void st_hilo(char* hi_p, char* lo_p, float4 v) {
    uint32_t h0, l0, h1, l1;
    split2h(v.x, v.y, h0, l0);
    split2h(v.z, v.w, h1, l1);
    *(uint2*)hi_p = make_uint2(h0, h1);
    *(uint2*)lo_p = make_uint2(l0, l1);
}
__device__ __forceinline__ void st_hi(char* hi_p, float4 v) {
    uint32_t h0 = pkh(v.x, v.y);
    uint32_t h1 = pkh(v.z, v.w);
    *(uint2*)hi_p = make_uint2(h0, h1);
}

#define STRD 144

// ================= k0: gwinv (8 CTAs) + reset counters =================
__global__ __launch_bounds__(256) void k0_prep(const float* __restrict__ gw) {
    __shared__ float red[8];
    int n = blockIdx.x, tid = threadIdx.x;
    if (n == 0 && tid < N_) g_cnt[tid] = 0;
    float s = 0.f;
    const float4* row = (const float4*)(gw + (size_t)n * C_);
    for (int i = tid; i < C_/4; i += 256) {
        float4 v = row[i];
        s += v.x*v.x + v.y*v.y + v.z*v.z + v.w*v.w;
    }
    #pragma unroll
    for (int o = 16; o; o >>= 1) s += __shfl_xor_sync(0xffffffffu, s, o);
    if ((tid & 31) == 0) red[tid >> 5] = s;
    __syncthreads();
    if (tid < 8) {
        s = red[tid];
        #pragma unroll
        for (int o = 4; o; o >>= 1) s += __shfl_xor_sync(0xffu, s, o);
        if (tid == 0) g_gwinv[n] = 1.f / fmaxf(sqrtf(s), 1e-12f);
    }
}

// ================= k1: gating dots via fp16 3-term mma (routing-safe), K-split 16 =================
#define K1_X_HI 0
#define K1_X_LO 18432
#define K1_W_HI 36864
__global__ __launch_bounds__(256, 3) void k1_mma(const float* __restrict__ x,
                                                 const float* __restrict__ gw) {
    __shared__ char sm[36864 + 2*2304];
    const int W_LO_O = 36864 + 2304;

    int tid = threadIdx.x, wid = tid >> 5, lid = tid & 31;
    int b0 = blockIdx.x * 128;
    int kb = blockIdx.y;

    uint32_t sb = smem_u32(sm);
    const float4* x4  = (const float4*)x;
    const float4* gw4 = (const float4*)gw;

    int ldr = tid >> 4;
    int ldc = tid & 15;

    uint32_t aoff = (uint32_t)((16*wid + (lid & 15))*STRD + (lid >> 4)*16);
    uint32_t boff = (uint32_t)(((lid & 7) + ((lid >> 4) & 1)*8)*STRD + ((lid >> 3) & 1)*16);

    float acc[4] = {0.f, 0.f, 0.f, 0.f};
    float sqr[8];
    #pragma unroll
    for (int j = 0; j < 8; j++) sqr[j] = 0.f;

    float4 xg[8], wg;
    #pragma unroll
    for (int j = 0; j < 8; j++) {
        int row = ldr + 16*j;
        xg[j] = __ldcs(&x4[(size_t)(b0 + row)*5120 + kb*320 + ldc]);
    }
    if (tid < 128) wg = gw4[(size_t)(tid >> 4)*5120 + kb*320 + (tid & 15)];
    #pragma unroll
    for (int j = 0; j < 8; j++) {
        int row = ldr + 16*j;
        sqr[j] += xg[j].x*xg[j].x + xg[j].y*xg[j].y + xg[j].z*xg[j].z + xg[j].w*xg[j].w;
        st_hilo(sm + K1_X_HI + row*STRD + ldc*8, sm + K1_X_LO + row*STRD + ldc*8, xg[j]);
    }
    if (tid < 128)
        st_hilo(sm + K1_W_HI + (tid >> 4)*STRD + (tid & 15)*8,
                sm + W_LO_O + (tid >> 4)*STRD + (tid & 15)*8, wg);
    __syncthreads();

    for (int ch = 0; ch < 20; ch++) {
        if (ch + 1 < 20) {
            #pragma unroll
            for (int j = 0; j < 8; j++) {
                int row = ldr + 16*j;
                xg[j] = __ldcs(&x4[(size_t)(b0 + row)*5120 + kb*320 + (ch+1)*16 + ldc]);
            }
            if (tid < 128) wg = gw4[(size_t)(tid >> 4)*5120 + kb*320 + (ch+1)*16 + (tid & 15)];
        }
        #pragma unroll
        for (int ks = 0; ks < 4; ks++) {
            uint32_t ah[4], al[4], bh[4], bl[4];
            ldsm_x4(ah, sb + K1_X_HI + aoff + ks*32);
            ldsm_x4(al, sb + K1_X_LO + aoff + ks*32);
            ldsm_x4(bh, sb + K1_W_HI + boff + ks*32);
            ldsm_x4(bl, sb + W_LO_O + boff + ks*32);
            mma_f16(acc, ah, bh);
            mma_f16(acc, al, bh);
            mma_f16(acc, ah, bl);
        }
        __syncthreads();
        if (ch + 1 < 20) {
            #pragma unroll
            for (int j = 0; j < 8; j++) {
                int row = ldr + 16*j;
                sqr[j] += xg[j].x*xg[j].x + xg[j].y*xg[j].y + xg[j].z*xg[j].z + xg[j].w*xg[j].w;
                st_hilo(sm + K1_X_HI + row*STRD + ldc*8, sm + K1_X_LO + row*STRD + ldc*8, xg[j]);
            }
            if (tid < 128)
                st_hilo(sm + K1_W_HI + (tid >> 4)*STRD + (tid & 15)*8,
                        sm + W_LO_O + (tid >> 4)*STRD + (tid & 15)*8, wg);
            __syncthreads();
        }
    }

    #pragma unroll
    for (int j = 0; j < 8; j++) {
        float s = sqr[j];
        #pragma unroll
        for (int o = 8; o; o >>= 1) s += __shfl_xor_sync(0xffffffffu, s, o);
        sqr[j] = s;
    }
    if ((tid & 15) == 0) {
        #pragma unroll
        for (int j = 0; j < 8; j++)
            g_xsqp[(size_t)kb*B_ + b0 + ldr + 16*j] = sqr[j];
    }
    {
        int r = lid >> 2, n0 = 2*(lid & 3);
        int m0 = b0 + wid*16 + r;
        float2* dp = (float2*)g_dotp;
        dp[(((size_t)kb*B_ + m0)*8 + n0) >> 1]     = make_float2(acc[0], acc[1]);
        dp[(((size_t)kb*B_ + m0 + 8)*8 + n0) >> 1] = make_float2(acc[2], acc[3]);
    }
}

// ================= k1b: sum partials + logits + gumbel + argmax + DIRECT scatter =================
// g_perm order within an expert region is irrelevant (each batch owns its output rows),
// so atomic slot allocation gives deterministic OUTPUT despite nondeterministic order.
__global__ void k1b_argmax(const float* __restrict__ u, const float* __restrict__ sigma_p) {
    int b = blockIdx.x * blockDim.x + threadIdx.x;
    if (b >= B_) return;
    float sigma = *sigma_p;
    float d[8];
    #pragma unroll
    for (int n = 0; n < 8; n++) d[n] = 0.f;
    float xs = 0.f;
    #pragma unroll
    for (int kb = 0; kb < KSPLIT; kb++) {
        const float4* p = (const float4*)(g_dotp + ((size_t)kb*B_ + b)*8);
        float4 a = p[0], c = p[1];
        d[0] += a.x; d[1] += a.y; d[2] += a.z; d[3] += a.w;
        d[4] += c.x; d[5] += c.y; d[6] += c.z; d[7] += c.w;
        xs += g_xsqp[(size_t)kb*B_ + b];
    }
    float invx = 1.f / fmaxf(sqrtf(xs), 1e-12f);
    const float4* u4 = (const float4*)(u + (size_t)b*8);
    float4 ua = u4[0], ub = u4[1];
    float uu[8] = {ua.x, ua.y, ua.z, ua.w, ub.x, ub.y, ub.z, ub.w};
    float best = -3.4e38f; int e = 0;
    #pragma unroll
    for (int n = 0; n < 8; n++) {
        float logit = sigma * d[n] * invx * g_gwinv[n];
        float gmb = -logf(-logf(uu[n] + 1e-12f) + 1e-12f);
        float z = logit + gmb;
        if (z > best) { best = z; e = n; }
    }
    int pos = atomicAdd(&g_cnt[e], 1);
    g_perm[e*B_ + pos] = b;
}

// ================= K3: fused warp-mma LoRA, single-fp16 operands (round-12 winner) =================
// smem: X_HI/MID_HI 0..18432, W_B0 18432..27648, W_B1 27648..36864
#define X_HI   0
#define MID_HI 0
#define W_B0   18432
#define W_B1   27648
#define DYN_SMEM 36864

__global__ __launch_bounds__(256, 2)
void k3_mma(const float* __restrict__ x, const float* __restrict__ dw,
            const float* __restrict__ uw, float* __restrict__ out) {
    extern __shared__ char sm[];
    __shared__ int bs_sh[GB];
    __shared__ int info[2];

    int tid = threadIdx.x, wid = tid >> 5, lid = tid & 31;

    if (tid == 0) {
        int rem = blockIdx.x; int e = -1, g = 0, start = 0;
        for (int n = 0; n < N_; n++) {
            int cnt = g_cnt[n];
            int ng = (cnt + GB - 1) / GB;
            if (rem < ng) { e = n; start = rem*GB;
                            g = cnt - start; if (g > GB) g = GB; break; }
            rem -= ng;
        }
        info[0] = e; info[1] = g;
        if (e >= 0) for (int i = 0; i < GB; i++) {
            int ii = i < g ? i : g - 1;
            bs_sh[i] = g_perm[e*B_ + start + ii];
        }
    }
    __syncthreads();
    int e = info[0], g = info[1];
    if (e < 0) return;

    uint32_t sb = smem_u32(sm);
    const float4* x4  = (const float4*)x;
    const float4* dw4 = (const float4*)dw;
    const float4* uw4 = (const float4*)uw;

    int ldr = tid >> 4;
    int ldc = tid & 15;

    uint32_t aoff = (uint32_t)((16*wid + (lid & 15))*STRD + (lid >> 4)*16);
    uint32_t boff = (uint32_t)(((lid & 7) + ((lid >> 4) & 1)*8)*STRD + ((lid >> 3) & 1)*16);

    // ---------------- phase 1: single-fp16 X and W ----------------
    float acc[8][4];
    #pragma unroll
    for (int i = 0; i < 8; i++)
        #pragma unroll
        for (int j = 0; j < 4; j++) acc[i][j] = 0.f;

    float4 xg[8], wg[4];
    #pragma unroll
    for (int j = 0; j < 8; j++) {
        int row = ldr + 16*j;
        int bb = bs_sh[row >> 4], f = row & 15;
        xg[j] = __ldcs(&x4[(size_t)(bb*16 + f)*320 + ldc]);
    }
    #pragma unroll
    for (int j = 0; j < 4; j++) {
        int row = ldr + 16*j;
        wg[j] = dw4[(size_t)(e*64 + row)*320 + ldc];
    }
    #pragma unroll
    for (int j = 0; j < 8; j++) {
        int row = ldr + 16*j;
        st_hi(sm + X_HI + row*STRD + ldc*8, xg[j]);
    }
    #pragma unroll
    for (int j = 0; j < 4; j++) {
        int row = ldr + 16*j;
        st_hi(sm + W_B0 + row*STRD + ldc*8, wg[j]);
    }
    __syncthreads();

    for (int ch = 0; ch < 20; ch++) {
        if (ch + 1 < 20) {
            #pragma unroll
            for (int j = 0; j < 8; j++) {
                int row = ldr + 16*j;
                int bb = bs_sh[row >> 4], f = row & 15;
                xg[j] = __ldcs(&x4[(size_t)(bb*16 + f)*320 + (ch+1)*16 + ldc]);
            }
            #pragma unroll
            for (int j = 0; j < 4; j++) {
                int row = ldr + 16*j;
                wg[j] = dw4[(size_t)(e*64 + row)*320 + (ch+1)*16 + ldc];
            }
        }
        #pragma unroll
        for (int ks = 0; ks < 4; ks++) {
            uint32_t ah[4];
            ldsm_x4(ah, sb + X_HI + aoff + ks*32);
            #pragma unroll
            for (int np = 0; np < 4; np++) {
                uint32_t bh[4];
                ldsm_x4(bh, sb + W_B0 + boff + np*16*STRD + ks*32);
                mma_f16(acc[2*np],   ah, bh);
                mma_f16(acc[2*np+1], ah, bh+2);
            }
        }
        __syncthreads();
        if (ch + 1 < 20) {
            #pragma unroll
            for (int j = 0; j < 8; j++) {
                int row = ldr + 16*j;
                st_hi(sm + X_HI + row*STRD + ldc*8, xg[j]);
            }
            #pragma unroll
            for (int j = 0; j < 4; j++) {
                int row = ldr + 16*j;
                st_hi(sm + W_B0 + row*STRD + ldc*8, wg[j]);
            }
            __syncthreads();
        }
    }

    // ---------------- mid -> smem fp16 (single) ----------------
    {
        int r0 = 16*wid + (lid >> 2);
        int co = (lid & 3)*4;
        #pragma unroll
        for (int nt = 0; nt < 8; nt++) {
            *(uint32_t*)(sm + MID_HI + r0*STRD + nt*16 + co)     = pkh(acc[nt][0], acc[nt][1]);
            *(uint32_t*)(sm + MID_HI + (r0+8)*STRD + nt*16 + co) = pkh(acc[nt][2], acc[nt][3]);
        }
    }
    __syncthreads();

    uint32_t mah[4][4];
    #pragma unroll
    for (int ks = 0; ks < 4; ks++)
        ldsm_x4(mah[ks], sb + MID_HI + aoff + ks*32);

    // ---------------- phase 2: double-buffered W, single-fp16 mid ----------------
    int bb_w = bs_sh[wid];
    float* outw = out + (size_t)(bb_w*16)*1280;

    #pragma unroll
    for (int j = 0; j < 4; j++) {
        int row = ldr + 16*j;
        wg[j] = uw4[(size_t)(e*1280 + row)*16 + ldc];
    }
    #pragma unroll
    for (int j = 0; j < 4; j++) {
        int row = ldr + 16*j;
        st_hi(sm + W_B0 + row*STRD + ldc*8, wg[j]);
    }
    __syncthreads();

    for (int i = 0; i < 20; i++) {
        uint32_t buf = (i & 1) ? W_B1 : W_B0;
        if (i + 1 < 20) {
            #pragma unroll
            for (int j = 0; j < 4; j++) {
                int row = ldr + 16*j;
                wg[j] = uw4[(size_t)(e*1280 + (i+1)*64 + row)*16 + ldc];
            }
        }
        float a2[8][4];
        #pragma unroll
        for (int p = 0; p < 8; p++)
            #pragma unroll
            for (int q = 0; q < 4; q++) a2[p][q] = 0.f;
        #pragma unroll
        for (int ks = 0; ks < 4; ks++) {
            #pragma unroll
            for (int np = 0; np < 4; np++) {
                uint32_t bh[4];
                ldsm_x4(bh, sb + buf + boff + np*16*STRD + ks*32);
                mma_f16(a2[2*np],   mah[ks], bh);
                mma_f16(a2[2*np+1], mah[ks], bh+2);
            }
        }
        if (wid < g) {
            int r0 = lid >> 2, c0 = (lid & 3)*2;
            #pragma unroll
            for (int nt = 0; nt < 8; nt++) {
                int col = i*64 + nt*8 + c0;
                __stcs((float2*)(outw + (size_t)r0*1280 + col),     make_float2(a2[nt][0], a2[nt][1]));
                __stcs((float2*)(outw + (size_t)(r0+8)*1280 + col), make_float2(a2[nt][2], a2[nt][3]));
            }
        }
        if (i + 1 < 20) {
            uint32_t nbuf = ((i+1) & 1) ? W_B1 : W_B0;
            #pragma unroll
            for (int j = 0; j < 4; j++) {
                int row = ldr + 16*j;
                st_hi(sm + nbuf + row*STRD + ldc*8, wg[j]);
            }
            __syncthreads();
        }
    }
}

// ================= launch =================
extern "C" void kernel_launch(void* const* d_in, const int* in_sizes, int n_in,
                              void* d_out, int out_size) {
    const float* x     = (const float*)d_in[0];
    const float* u     = (const float*)d_in[1];
    const float* gw    = (const float*)d_in[2];
    const float* sigma = (const float*)d_in[3];
    const float* dw    = (const float*)d_in[4];
    const float* uw    = (const float*)d_in[5];
    float* out = (float*)d_out;

    cudaFuncSetAttribute(k3_mma, cudaFuncAttributeMaxDynamicSharedMemorySize, DYN_SMEM);

    k0_prep<<<N_, 256>>>(gw);
    k1_mma<<<dim3(32, 16), 256>>>(x, gw);
    k1b_argmax<<<B_/256, 256>>>(u, sigma);
    k3_mma<<<B_/GB + N_, 256, DYN_SMEM>>>(x, dw, uw, out);
}

// round 16
// speedup vs baseline: 1.2009x; 1.0257x over previous
#include <cuda_runtime.h>
#include <cuda_fp16.h>
#include <math.h>
#include <stdint.h>

#define B_ 4096
#define F_ 16
#define H_ 1280
#define N_ 8
#define R_ 64
#define C_ (F_*H_)   // 20480
#define GB 8
#define KSPLIT 10    // 320 CTAs -> single wave at 3 CTAs/SM

// ---------------- device scratch ----------------
__device__ float g_dotp[KSPLIT*B_*8];
__device__ float g_xsqp[KSPLIT*B_];
__device__ float g_gwsqp[KSPLIT*N_];
__device__ int   g_cnt[N_];
__device__ int   g_perm[N_*B_];   // per-expert fixed regions; order within region irrelevant

// ---------------- helpers ----------------
__device__ __forceinline__ uint32_t smem_u32(const void* p) {
    uint32_t a;
    asm("{ .reg .u64 t; cvta.to.shared.u64 t, %1; cvt.u32.u64 %0, t; }" : "=r"(a) : "l"(p));
    return a;
}
__device__ __forceinline__ void ldsm_x4(uint32_t* r, uint32_t addr) {
    asm volatile("ldmatrix.sync.aligned.m8n8.x4.shared.b16 {%0,%1,%2,%3}, [%4];"
                 : "=r"(r[0]), "=r"(r[1]), "=r"(r[2]), "=r"(r[3]) : "r"(addr));
}
__device__ __forceinline__ void mma_f16(float* c, const uint32_t* a, const uint32_t* b) {
    asm volatile("mma.sync.aligned.m16n8k16.row.col.f32.f16.f16.f32 "
        "{%0,%1,%2,%3}, {%4,%5,%6,%7}, {%8,%9}, {%0,%1,%2,%3};"
        : "+f"(c[0]), "+f"(c[1]), "+f"(c[2]), "+f"(c[3])
        : "r"(a[0]), "r"(a[1]), "r"(a[2]), "r"(a[3]), "r"(b[0]), "r"(b[1]));
}
__device__ __forceinline__ uint32_t pkh(float lo, float hi) {
    uint32_t r;
    asm("cvt.rn.f16x2.f32 %0, %1, %2;" : "=r"(r) : "f"(hi), "f"(lo));
    return r;
}
__device__ __forceinline__ void split2h(float a, float b, uint32_t& h, uint32_t& l) {
    h = pkh(a, b);
    __half2 hh = *reinterpret_cast<__half2*>(&h);
    float2 f = __half22float2(hh);
    l = pkh(a - f.x, b - f.y);
}
__device__ __forceinline__ void st_hilo(char* hi_p, char* lo_p, float4 v) {
    uint32_t h0, l0, h1, l1;
    split2h(v.x, v.y, h0, l0);
    split2h(v.z, v.w, h1, l1);
    *(uint2*)hi_p = make_uint2(h0, h1);
    *(uint2*)lo_p = make_uint2(l0, l1);
}
__device__ __forceinline__ void st_hi(char* hi_p, float4 v) {
    uint32_t h0 = pkh(v.x, v.y);
    uint32_t h1 = pkh(v.z, v.w);
    *(uint2*)hi_p = make_uint2(h0, h1);
}

#define STRD 144

// ================= k1: gating dots via fp16 3-term mma (routing-safe), K-split 10 =================
// Byproducts: per-kb x sq-norm partials, per-kb gw sq-norm partials (identical-value writes
// across bx CTAs), and g_cnt reset from CTA (0,0). k0 is gone.
#define K1_X_HI 0
#define K1_X_LO 18432
#define K1_W_HI 36864
__global__ __launch_bounds__(256, 3) void k1_mma(const float* __restrict__ x,
                                                 const float* __restrict__ gw) {
    __shared__ char sm[36864 + 2*2304];
    const int W_LO_O = 36864 + 2304;

    int tid = threadIdx.x, wid = tid >> 5, lid = tid & 31;
    int b0 = blockIdx.x * 128;
    int kb = blockIdx.y;

    if (blockIdx.x == 0 && kb == 0 && tid < N_) g_cnt[tid] = 0;

    uint32_t sb = smem_u32(sm);
    const float4* x4  = (const float4*)x;
    const float4* gw4 = (const float4*)gw;

    int ldr = tid >> 4;
    int ldc = tid & 15;

    uint32_t aoff = (uint32_t)((16*wid + (lid & 15))*STRD + (lid >> 4)*16);
    uint32_t boff = (uint32_t)(((lid & 7) + ((lid >> 4) & 1)*8)*STRD + ((lid >> 3) & 1)*16);

    float acc[4] = {0.f, 0.f, 0.f, 0.f};
    float sqr[8];
    #pragma unroll
    for (int j = 0; j < 8; j++) sqr[j] = 0.f;
    float sqw = 0.f;

    float4 xg[8], wg;
    #pragma unroll
    for (int j = 0; j < 8; j++) {
        int row = ldr + 16*j;
        xg[j] = __ldcs(&x4[(size_t)(b0 + row)*5120 + kb*512 + ldc]);
    }
    if (tid < 128) wg = gw4[(size_t)(tid >> 4)*5120 + kb*512 + (tid & 15)];
    #pragma unroll
    for (int j = 0; j < 8; j++) {
        int row = ldr + 16*j;
        sqr[j] += xg[j].x*xg[j].x + xg[j].y*xg[j].y + xg[j].z*xg[j].z + xg[j].w*xg[j].w;
        st_hilo(sm + K1_X_HI + row*STRD + ldc*8, sm + K1_X_LO + row*STRD + ldc*8, xg[j]);
    }
    if (tid < 128) {
        sqw += wg.x*wg.x + wg.y*wg.y + wg.z*wg.z + wg.w*wg.w;
        st_hilo(sm + K1_W_HI + (tid >> 4)*STRD + (tid & 15)*8,
                sm + W_LO_O + (tid >> 4)*STRD + (tid & 15)*8, wg);
    }
    __syncthreads();

    for (int ch = 0; ch < 32; ch++) {
        if (ch + 1 < 32) {
            #pragma unroll
            for (int j = 0; j < 8; j++) {
                int row = ldr + 16*j;
                xg[j] = __ldcs(&x4[(size_t)(b0 + row)*5120 + kb*512 + (ch+1)*16 + ldc]);
            }
            if (tid < 128) wg = gw4[(size_t)(tid >> 4)*5120 + kb*512 + (ch+1)*16 + (tid & 15)];
        }
        #pragma unroll
        for (int ks = 0; ks < 4; ks++) {
            uint32_t ah[4], al[4], bh[4], bl[4];
            ldsm_x4(ah, sb + K1_X_HI + aoff + ks*32);
            ldsm_x4(al, sb + K1_X_LO + aoff + ks*32);
            ldsm_x4(bh, sb + K1_W_HI + boff + ks*32);
            ldsm_x4(bl, sb + W_LO_O + boff + ks*32);
            mma_f16(acc, ah, bh);
            mma_f16(acc, al, bh);
            mma_f16(acc, ah, bl);
        }
        __syncthreads();
        if (ch + 1 < 32) {
            #pragma unroll
            for (int j = 0; j < 8; j++) {
                int row = ldr + 16*j;
                sqr[j] += xg[j].x*xg[j].x + xg[j].y*xg[j].y + xg[j].z*xg[j].z + xg[j].w*xg[j].w;
                st_hilo(sm + K1_X_HI + row*STRD + ldc*8, sm + K1_X_LO + row*STRD + ldc*8, xg[j]);
            }
            if (tid < 128) {
                sqw += wg.x*wg.x + wg.y*wg.y + wg.z*wg.z + wg.w*wg.w;
                st_hilo(sm + K1_W_HI + (tid >> 4)*STRD + (tid & 15)*8,
                        sm + W_LO_O + (tid >> 4)*STRD + (tid & 15)*8, wg);
            }
            __syncthreads();
        }
    }

    // x sq-norm partials: reduce 16-lane groups
    #pragma unroll
    for (int j = 0; j < 8; j++) {
        float s = sqr[j];
        #pragma unroll
        for (int o = 8; o; o >>= 1) s += __shfl_xor_sync(0xffffffffu, s, o);
        sqr[j] = s;
    }
    if ((tid & 15) == 0) {
        #pragma unroll
        for (int j = 0; j < 8; j++)
            g_xsqp[(size_t)kb*B_ + b0 + ldr + 16*j] = sqr[j];
    }
    // gw sq-norm partials (same value from every bx CTA; benign identical write)
    if (tid < 128) {
        float s = sqw;
        #pragma unroll
        for (int o = 8; o; o >>= 1) s += __shfl_xor_sync(0xffffffffu, s, o);
        if ((tid & 15) == 0) g_gwsqp[kb*N_ + (tid >> 4)] = s;
    }
    {
        int r = lid >> 2, n0 = 2*(lid & 3);
        int m0 = b0 + wid*16 + r;
        float2* dp = (float2*)g_dotp;
        dp[(((size_t)kb*B_ + m0)*8 + n0) >> 1]     = make_float2(acc[0], acc[1]);
        dp[(((size_t)kb*B_ + m0 + 8)*8 + n0) >> 1] = make_float2(acc[2], acc[3]);
    }
}

// ================= k1b: gwinv + sum partials + logits + gumbel + argmax + direct scatter =================
__global__ void k1b_argmax(const float* __restrict__ u, const float* __restrict__ sigma_p) {
    __shared__ float gwi[N_];
    int tid = threadIdx.x;
    if (tid < N_) {
        float s = 0.f;
        #pragma unroll
        for (int kb = 0; kb < KSPLIT; kb++) s += g_gwsqp[kb*N_ + tid];
        gwi[tid] = 1.f / fmaxf(sqrtf(s), 1e-12f);
    }
    __syncthreads();

    int b = blockIdx.x * blockDim.x + tid;
    if (b >= B_) return;
    float sigma = *sigma_p;
    float d[8];
    #pragma unroll
    for (int n = 0; n < 8; n++) d[n] = 0.f;
    float xs = 0.f;
    #pragma unroll
    for (int kb = 0; kb < KSPLIT; kb++) {
        const float4* p = (const float4*)(g_dotp + ((size_t)kb*B_ + b)*8);
        float4 a = p[0], c = p[1];
        d[0] += a.x; d[1] += a.y; d[2] += a.z; d[3] += a.w;
        d[4] += c.x; d[5] += c.y; d[6] += c.z; d[7] += c.w;
        xs += g_xsqp[(size_t)kb*B_ + b];
    }
    float invx = 1.f / fmaxf(sqrtf(xs), 1e-12f);
    const float4* u4 = (const float4*)(u + (size_t)b*8);
    float4 ua = u4[0], ub = u4[1];
    float uu[8] = {ua.x, ua.y, ua.z, ua.w, ub.x, ub.y, ub.z, ub.w};
    float best = -3.4e38f; int e = 0;
    #pragma unroll
    for (int n = 0; n < 8; n++) {
        float logit = sigma * d[n] * invx * gwi[n];
        float gmb = -logf(-logf(uu[n] + 1e-12f) + 1e-12f);
        float z = logit + gmb;
        if (z > best) { best = z; e = n; }
    }
    int pos = atomicAdd(&g_cnt[e], 1);
    g_perm[e*B_ + pos] = b;
}

// ================= K3: fused warp-mma LoRA, single-fp16 operands (round-15, untouched) =================
// smem: X_HI/MID_HI 0..18432, W_B0 18432..27648, W_B1 27648..36864
#define X_HI   0
#define MID_HI 0
#define W_B0   18432
#define W_B1   27648
#define DYN_SMEM 36864

__global__ __launch_bounds__(256, 2)
void k3_mma(const float* __restrict__ x, const float* __restrict__ dw,
            const float* __restrict__ uw, float* __restrict__ out) {
    extern __shared__ char sm[];
    __shared__ int bs_sh[GB];
    __shared__ int info[2];

    int tid = threadIdx.x, wid = tid >> 5, lid = tid & 31;

    if (tid == 0) {
        int rem = blockIdx.x; int e = -1, g = 0, start = 0;
        for (int n = 0; n < N_; n++) {
            int cnt = g_cnt[n];
            int ng = (cnt + GB - 1) / GB;
            if (rem < ng) { e = n; start = rem*GB;
                            g = cnt - start; if (g > GB) g = GB; break; }
            rem -= ng;
        }
        info[0] = e; info[1] = g;
        if (e >= 0) for (int i = 0; i < GB; i++) {
            int ii = i < g ? i : g - 1;
            bs_sh[i] = g_perm[e*B_ + start + ii];
        }
    }
    __syncthreads();
    int e = info[0], g = info[1];
    if (e < 0) return;

    uint32_t sb = smem_u32(sm);
    const float4* x4  = (const float4*)x;
    const float4* dw4 = (const float4*)dw;
    const float4* uw4 = (const float4*)uw;

    int ldr = tid >> 4;
    int ldc = tid & 15;

    uint32_t aoff = (uint32_t)((16*wid + (lid & 15))*STRD + (lid >> 4)*16);
    uint32_t boff = (uint32_t)(((lid & 7) + ((lid >> 4) & 1)*8)*STRD + ((lid >> 3) & 1)*16);

    // ---------------- phase 1: single-fp16 X and W ----------------
    float acc[8][4];
    #pragma unroll
    for (int i = 0; i < 8; i++)
        #pragma unroll
        for (int j = 0; j < 4; j++) acc[i][j] = 0.f;

    float4 xg[8], wg[4];
    #pragma unroll
    for (int j = 0; j < 8; j++) {
        int row = ldr + 16*j;
        int bb = bs_sh[row >> 4], f = row & 15;
        xg[j] = __ldcs(&x4[(size_t)(bb*16 + f)*320 + ldc]);
    }
    #pragma unroll
    for (int j = 0; j < 4; j++) {
        int row = ldr + 16*j;
        wg[j] = dw4[(size_t)(e*64 + row)*320 + ldc];
    }
    #pragma unroll
    for (int j = 0; j < 8; j++) {
        int row = ldr + 16*j;
        st_hi(sm + X_HI + row*STRD + ldc*8, xg[j]);
    }
    #pragma unroll
    for (int j = 0; j < 4; j++) {
        int row = ldr + 16*j;
        st_hi(sm + W_B0 + row*STRD + ldc*8, wg[j]);
    }
    __syncthreads();

    for (int ch = 0; ch < 20; ch++) {
        if (ch + 1 < 20) {
            #pragma unroll
            for (int j = 0; j < 8; j++) {
                int row = ldr + 16*j;
                int bb = bs_sh[row >> 4], f = row & 15;
                xg[j] = __ldcs(&x4[(size_t)(bb*16 + f)*320 + (ch+1)*16 + ldc]);
            }
            #pragma unroll
            for (int j = 0; j < 4; j++) {
                int row = ldr + 16*j;
                wg[j] = dw4[(size_t)(e*64 + row)*320 + (ch+1)*16 + ldc];
            }
        }
        #pragma unroll
        for (int ks = 0; ks < 4; ks++) {
            uint32_t ah[4];
            ldsm_x4(ah, sb + X_HI + aoff + ks*32);
            #pragma unroll
            for (int np = 0; np < 4; np++) {
                uint32_t bh[4];
                ldsm_x4(bh, sb + W_B0 + boff + np*16*STRD + ks*32);
                mma_f16(acc[2*np],   ah, bh);
                mma_f16(acc[2*np+1], ah, bh+2);
            }
        }
        __syncthreads();
        if (ch + 1 < 20) {
            #pragma unroll
            for (int j = 0; j < 8; j++) {
                int row = ldr + 16*j;
                st_hi(sm + X_HI + row*STRD + ldc*8, xg[j]);
            }
            #pragma unroll
            for (int j = 0; j < 4; j++) {
                int row = ldr + 16*j;
                st_hi(sm + W_B0 + row*STRD + ldc*8, wg[j]);
            }
            __syncthreads();
        }
    }

    // ---------------- mid -> smem fp16 (single) ----------------
    {
        int r0 = 16*wid + (lid >> 2);
        int co = (lid & 3)*4;
        #pragma unroll
        for (int nt = 0; nt < 8; nt++) {
            *(uint32_t*)(sm + MID_HI + r0*STRD + nt*16 + co)     = pkh(acc[nt][0], acc[nt][1]);
            *(uint32_t*)(sm + MID_HI + (r0+8)*STRD + nt*16 + co) = pkh(acc[nt][2], acc[nt][3]);
        }
    }
    __syncthreads();

    uint32_t mah[4][4];
    #pragma unroll
    for (int ks = 0; ks < 4; ks++)
        ldsm_x4(mah[ks], sb + MID_HI + aoff + ks*32);

    // ---------------- phase 2: double-buffered W, single-fp16 mid ----------------
    int bb_w = bs_sh[wid];
    float* outw = out + (size_t)(bb_w*16)*1280;

    #pragma unroll
    for (int j = 0; j < 4; j++) {
        int row = ldr + 16*j;
        wg[j] = uw4[(size_t)(e*1280 + row)*16 + ldc];
    }
    #pragma unroll
    for (int j = 0; j < 4; j++) {
        int row = ldr + 16*j;
        st_hi(sm + W_B0 + row*STRD + ldc*8, wg[j]);
    }
    __syncthreads();

    for (int i = 0; i < 20; i++) {
        uint32_t buf = (i & 1) ? W_B1 : W_B0;
        if (i + 1 < 20) {
            #pragma unroll
            for (int j = 0; j < 4; j++) {
                int row = ldr + 16*j;
                wg[j] = uw4[(size_t)(e*1280 + (i+1)*64 + row)*16 + ldc];
            }
        }
        float a2[8][4];
        #pragma unroll
        for (int p = 0; p < 8; p++)
            #pragma unroll
            for (int q = 0; q < 4; q++) a2[p][q] = 0.f;
        #pragma unroll
        for (int ks = 0; ks < 4; ks++) {
            #pragma unroll
            for (int np = 0; np < 4; np++) {
                uint32_t bh[4];
                ldsm_x4(bh, sb + buf + boff + np*16*STRD + ks*32);
                mma_f16(a2[2*np],   mah[ks], bh);
                mma_f16(a2[2*np+1], mah[ks], bh+2);
            }
        }
        if (wid < g) {
            int r0 = lid >> 2, c0 = (lid & 3)*2;
            #pragma unroll
            for (int nt = 0; nt < 8; nt++) {
                int col = i*64 + nt*8 + c0;
                __stcs((float2*)(outw + (size_t)r0*1280 + col),     make_float2(a2[nt][0], a2[nt][1]));
                __stcs((float2*)(outw + (size_t)(r0+8)*1280 + col), make_float2(a2[nt][2], a2[nt][3]));
            }
        }
        if (i + 1 < 20) {
            uint32_t nbuf = ((i+1) & 1) ? W_B1 : W_B0;
            #pragma unroll
            for (int j = 0; j < 4; j++) {
                int row = ldr + 16*j;
                st_hi(sm + nbuf + row*STRD + ldc*8, wg[j]);
            }
            __syncthreads();
        }
    }
}

// ================= launch =================
extern "C" void kernel_launch(void* const* d_in, const int* in_sizes, int n_in,
                              void* d_out, int out_size) {
    const float* x     = (const float*)d_in[0];
    const float* u     = (const float*)d_in[1];
    const float* gw    = (const float*)d_in[2];
    const float* sigma = (const float*)d_in[3];
    const float* dw    = (const float*)d_in[4];
    const float* uw    = (const float*)d_in[5];
    float* out = (float*)d_out;

    cudaFuncSetAttribute(k3_mma, cudaFuncAttributeMaxDynamicSharedMemorySize, DYN_SMEM);

    k1_mma<<<dim3(32, KSPLIT), 256>>>(x, gw);
    k1b_argmax<<<B_/256, 256>>>(u, sigma);
    k3_mma<<<B_/GB + N_, 256, DYN_SMEM>>>(x, dw, uw, out);
}